// round 5
// baseline (speedup 1.0000x reference)
#include <cuda_runtime.h>
#include <cstdint>

// Problem constants (fixed by setup_inputs)
#define B 8
#define L 2048
#define H 8
#define D 64
#define BH (B*H)

// Scratch (device globals — no allocation allowed)
__device__ float g_M[BH * L];        // sparsity measure per (b,h,q)
__device__ int   g_top[BH * 64];     // top-u query indices per (b,h)  (u <= 64)
__device__ float g_vmean[BH * D];    // mean of V over L per (b,h,d)

// ---------------------------------------------------------------------------
// Kernel A: M[b,h,q] = max_s(QK_s) - mean_s(QK_s) over sampled keys.
// One warp per (b,h,q). lane holds d=lane and d=lane+32 of Q.
// ---------------------------------------------------------------------------
__global__ void __launch_bounds__(256) kA_mscore(
    const float* __restrict__ Q, const float* __restrict__ K,
    const int* __restrict__ idx, int SK)
{
    int wid  = (blockIdx.x * blockDim.x + threadIdx.x) >> 5;   // [0, BH*L)
    int lane = threadIdx.x & 31;
    int q  = wid & (L - 1);
    int bh = wid >> 11;                 // L = 2048 = 2^11
    int b  = bh >> 3, h = bh & 7;       // H = 8

    const float* qp = Q + ((size_t)(b * L + q) * H + h) * D;
    float q0 = qp[lane], q1 = qp[lane + 32];

    const int* ip = idx + (size_t)q * SK;
    float mx = -3.402823466e38f;
    float sm = 0.f;

    #pragma unroll 4
    for (int s = 0; s < SK; ++s) {
        int kq = ip[s];
        const float* kp = K + ((size_t)(b * L + kq) * H + h) * D;
        float v = q0 * kp[lane] + q1 * kp[lane + 32];
        v += __shfl_xor_sync(0xffffffffu, v, 16);
        v += __shfl_xor_sync(0xffffffffu, v, 8);
        v += __shfl_xor_sync(0xffffffffu, v, 4);
        v += __shfl_xor_sync(0xffffffffu, v, 2);
        v += __shfl_xor_sync(0xffffffffu, v, 1);
        mx = fmaxf(mx, v);
        sm += v;
    }
    if (lane == 0)
        g_M[wid] = mx - sm / (float)SK;
}

// ---------------------------------------------------------------------------
// Kernel B: top-U argmax per (b,h) (iterative, ties -> lower index like jax).
// One block per (b,h).
// ---------------------------------------------------------------------------
__global__ void __launch_bounds__(256) kB_topk(int U)
{
    __shared__ float sm[L];
    __shared__ float rv[256];
    __shared__ int   ri[256];
    int bh = blockIdx.x, t = threadIdx.x;

    for (int i = t; i < L; i += 256) sm[i] = g_M[(size_t)bh * L + i];
    __syncthreads();

    for (int it = 0; it < U; ++it) {
        float bv = -3.402823466e38f; int bi = 0x7fffffff;
        for (int i = t; i < L; i += 256) {
            float v = sm[i];
            if (v > bv || (v == bv && i < bi)) { bv = v; bi = i; }
        }
        rv[t] = bv; ri[t] = bi;
        __syncthreads();
        for (int s = 128; s > 0; s >>= 1) {
            if (t < s) {
                float v2 = rv[t + s]; int i2 = ri[t + s];
                if (v2 > rv[t] || (v2 == rv[t] && i2 < ri[t])) { rv[t] = v2; ri[t] = i2; }
            }
            __syncthreads();
        }
        if (t == 0) {
            g_top[bh * 64 + it] = ri[0];
            sm[ri[0]] = -3.402823466e38f;
        }
        __syncthreads();
    }
}

// ---------------------------------------------------------------------------
// Kernel C: Vmean[b,h,d] = mean over l of V[b,l,h,d]. One block per (b,h).
// ---------------------------------------------------------------------------
__global__ void __launch_bounds__(256) kC_vmean(const float* __restrict__ V)
{
    __shared__ float part[4][D];
    int bh = blockIdx.x, b = bh >> 3, h = bh & 7;
    int d = threadIdx.x & 63, g = threadIdx.x >> 6;
    float s = 0.f;
    for (int l = g; l < L; l += 4)
        s += V[((size_t)(b * L + l) * H + h) * D + d];
    part[g][d] = s;
    __syncthreads();
    if (threadIdx.x < D) {
        float tot = part[0][d] + part[1][d] + part[2][d] + part[3][d];
        g_vmean[bh * D + d] = tot * (1.0f / (float)L);
    }
}

// ---------------------------------------------------------------------------
// Kernel D: fill output with broadcast Vmean (float4 vectorized).
// out[b, l, h*64+d] = vmean[b,h,d]
// ---------------------------------------------------------------------------
__global__ void __launch_bounds__(256) kD_fill(float4* __restrict__ out4)
{
    int i = blockIdx.x * blockDim.x + threadIdx.x;     // [0, B*L*128)
    int j   = i & 127;          // 128 float4 per (b,l) row
    int row = i >> 7;
    int b = row >> 11, l = row & (L - 1);
    (void)l;
    int h = j >> 4, d4 = j & 15;
    const float4* vm4 = (const float4*)g_vmean;
    out4[i] = vm4[(b * H + h) * 16 + d4];
}

// ---------------------------------------------------------------------------
// Kernel E: full attention for 8 selected queries per block.
//   scores (in smem p) -> softmax (unnormalized exps + denom) -> ctx = p@V / den
// grid = BH * UT blocks, 256 threads, dynamic smem ~76KB.
// ---------------------------------------------------------------------------
#define UQ 8
#define SMEM_E ((UQ*L + UQ*D + 4*UQ*D + UQ) * 4)

__global__ void __launch_bounds__(256) kE_attn(
    const float* __restrict__ Q, const float* __restrict__ K,
    const float* __restrict__ V, float* __restrict__ out, int U, int UT)
{
    extern __shared__ float sh[];
    float* p    = sh;                    // [UQ][L] unnormalized probs
    float* Qs   = p + UQ * L;            // [UQ][D]
    float* red  = Qs + UQ * D;           // [4][UQ][D]
    float* sden = red + 4 * UQ * D;      // [UQ]
    __shared__ int qidx[UQ];

    int bh = blockIdx.x / UT, ut = blockIdx.x % UT;
    int b = bh >> 3, h = bh & 7;
    int t = threadIdx.x;
    int u0 = ut * UQ;
    int nq = U - u0; if (nq > UQ) nq = UQ;

    if (t < UQ) qidx[t] = (t < nq) ? g_top[bh * 64 + u0 + t] : 0;
    __syncthreads();

    // Load (or zero) Q rows
    for (int i = t; i < UQ * D; i += 256) {
        int j = i >> 6;
        Qs[i] = (j < nq) ? Q[((size_t)(b * L + qidx[j]) * H + h) * D + (i & 63)] : 0.f;
    }
    __syncthreads();

    // Pass 1: scores into smem.  Each thread owns k = t + 256*m.
    const float scale = 0.125f;  // 1/sqrt(64)
    for (int k = t; k < L; k += 256) {
        const float4* kp = (const float4*)(K + ((size_t)(b * L + k) * H + h) * D);
        float accj[UQ];
        #pragma unroll
        for (int j = 0; j < UQ; ++j) accj[j] = 0.f;
        #pragma unroll
        for (int c = 0; c < 4; ++c) {
            float4 k0 = kp[c*4+0], k1 = kp[c*4+1], k2 = kp[c*4+2], k3 = kp[c*4+3];
            #pragma unroll
            for (int j = 0; j < UQ; ++j) {
                const float4* qf = (const float4*)(Qs + j * D) + c * 4;
                float4 q0 = qf[0], q1 = qf[1], q2 = qf[2], q3 = qf[3];
                accj[j] += q0.x*k0.x + q0.y*k0.y + q0.z*k0.z + q0.w*k0.w
                         + q1.x*k1.x + q1.y*k1.y + q1.z*k1.z + q1.w*k1.w
                         + q2.x*k2.x + q2.y*k2.y + q2.z*k2.z + q2.w*k2.w
                         + q3.x*k3.x + q3.y*k3.y + q3.z*k3.z + q3.w*k3.w;
            }
        }
        #pragma unroll
        for (int j = 0; j < UQ; ++j) p[j * L + k] = accj[j] * scale;
    }
    __syncthreads();

    // Pass 2: softmax per query row (warp w handles row w).
    int w = t >> 5, lane = t & 31;
    if (w < nq) {
        float* pr = p + w * L;
        float m = -3.402823466e38f;
        for (int k = lane; k < L; k += 32) m = fmaxf(m, pr[k]);
        #pragma unroll
        for (int o = 16; o; o >>= 1) m = fmaxf(m, __shfl_xor_sync(0xffffffffu, m, o));
        float s = 0.f;
        for (int k = lane; k < L; k += 32) {
            float e = __expf(pr[k] - m);
            pr[k] = e;
            s += e;
        }
        #pragma unroll
        for (int o = 16; o; o >>= 1) s += __shfl_xor_sync(0xffffffffu, s, o);
        if (lane == 0) sden[w] = s;
    }
    __syncthreads();

    // Pass 3: ctx[j][d] = sum_k p[j][k] * V[k][d]
    int d = t & 63, g = t >> 6;
    float acc[UQ];
    #pragma unroll
    for (int j = 0; j < UQ; ++j) acc[j] = 0.f;
    for (int kb = g * 4; kb < L; kb += 16) {
        size_t vb = ((size_t)(b * L + kb) * H + h) * D + d;
        float v0 = V[vb];
        float v1 = V[vb + (size_t)H * D];
        float v2 = V[vb + (size_t)2 * H * D];
        float v3 = V[vb + (size_t)3 * H * D];
        #pragma unroll
        for (int j = 0; j < UQ; ++j) {
            float4 pv = *(const float4*)(p + j * L + kb);   // warp-uniform -> broadcast
            acc[j] += pv.x * v0 + pv.y * v1 + pv.z * v2 + pv.w * v3;
        }
    }
    #pragma unroll
    for (int j = 0; j < UQ; ++j) red[(g * UQ + j) * D + d] = acc[j];
    __syncthreads();

    for (int i = t; i < nq * D; i += 256) {
        int j = i >> 6, dd = i & 63;
        float s = red[(0 * UQ + j) * D + dd] + red[(1 * UQ + j) * D + dd]
                + red[(2 * UQ + j) * D + dd] + red[(3 * UQ + j) * D + dd];
        out[((size_t)(b * L + qidx[j]) * H + h) * D + dd] = s / sden[j];
    }
}

// ---------------------------------------------------------------------------
extern "C" void kernel_launch(void* const* d_in, const int* in_sizes, int n_in,
                              void* d_out, int out_size)
{
    const float* Q   = (const float*)d_in[0];
    const float* K   = (const float*)d_in[1];
    const float* V   = (const float*)d_in[2];
    const int*   idx = (const int*)d_in[3];
    float* out = (float*)d_out;

    int SK = in_sizes[3] / L;     // sample_k (= 40)
    int U  = SK;                  // u has the same formula (L_Q == L_K)
    if (U > 64) U = 64;
    int UT = (U + UQ - 1) / UQ;   // u-tiles per (b,h)

    // A: M scores (gathered QK over samples)
    kA_mscore<<<(BH * L) / 8, 256>>>(Q, K, idx, SK);
    // C: V mean per (b,h,d)
    kC_vmean<<<BH, 256>>>(V);
    // B: top-U query selection per (b,h)
    kB_topk<<<BH, 256>>>(U);
    // D: broadcast-fill output with Vmean
    kD_fill<<<(B * L * 128) / 256, 256>>>((float4*)out);
    // E: full attention for selected queries, overwrite their rows
    cudaFuncSetAttribute(kE_attn, cudaFuncAttributeMaxDynamicSharedMemorySize, SMEM_E);
    kE_attn<<<BH * UT, 256, SMEM_E>>>(Q, K, V, out, U, UT);
}